// round 7
// baseline (speedup 1.0000x reference)
#include <cuda_runtime.h>
#include <cuda_bf16.h>
#include <math.h>
#include <stdint.h>

// Problem constants
#define Bsz 16
#define CIn 32
#define COn 32
#define Hn  256
#define Wn  256
#define KM  32
#define SXn 64
#define RTOT (Bsz*CIn*Hn)   // 131072 rows

// ============================ tables / scratch ============================
// fwdW basis  [kc(4)][n(64)][72pad]  bf16 hi/lo
__device__ __align__(16) __nv_bfloat16 g_BWh[4*64*72], g_BWl[4*64*72];
// irfft basis [nh(2)][wn(128)][72pad] bf16 hi/lo
__device__ __align__(16) __nv_bfloat16 g_BIh[2*128*72], g_BIl[2*128*72];
// fwdH A tables: TH[sx][h] chunked [kc(4)][sx(64)][72pad]; re=cos, im=-sin
__device__ __align__(16) __nv_bfloat16 g_THr_h[4*64*72], g_THr_l[4*64*72];
__device__ __align__(16) __nv_bfloat16 g_THi_h[4*64*72], g_THi_l[4*64*72];
// invH A tables: conj(TH)^T [hh(2)][hn(128)][72pad]; re=cos, im=+sin
__device__ __align__(16) __nv_bfloat16 g_TIr_h[2*128*72], g_TIr_l[2*128*72];
__device__ __align__(16) __nv_bfloat16 g_TIi_h[2*128*72], g_TIi_l[2*128*72];

__device__ float2 g_Xw[(size_t)RTOT*KM];
__device__ float2 g_Xf[(size_t)Bsz*CIn*SXn*KM];
__device__ float2 g_Of[(size_t)Bsz*COn*SXn*KM];
__device__ float2 g_Tmp[(size_t)Bsz*COn*Hn*KM];
__device__ float2 g_Wt [2*1024*1024];
__device__ float2 g_Wet[2*1024*1024];

// ============================ helpers ============================
__device__ __forceinline__ uint32_t pack_bf(__nv_bfloat16 a, __nv_bfloat16 b) {
    return (uint32_t)__bfloat16_as_ushort(a) | ((uint32_t)__bfloat16_as_ushort(b) << 16);
}
__device__ __forceinline__ void split_bf(float v, __nv_bfloat16& h, __nv_bfloat16& l) {
    h = __float2bfloat16(v);
    l = __float2bfloat16(v - __bfloat162float(h));
}
__device__ __forceinline__ void mma16816(float* c, const uint32_t* a, const uint32_t* b) {
    asm volatile("mma.sync.aligned.m16n8k16.row.col.f32.bf16.bf16.f32 "
        "{%0,%1,%2,%3}, {%4,%5,%6,%7}, {%8,%9}, {%0,%1,%2,%3};"
        : "+f"(c[0]), "+f"(c[1]), "+f"(c[2]), "+f"(c[3])
        : "r"(a[0]), "r"(a[1]), "r"(a[2]), "r"(a[3]), "r"(b[0]), "r"(b[1]));
}

#define SEG 18432   // 4*64*72 == 2*128*72

__global__ void k_init() {
    int t = blockIdx.x * blockDim.x + threadIdx.x;
    int seg = t / SEG, r = t % SEG;
    if (seg == 0) {                      // fwdW basis
        int kc = r / (64*72);
        int rem = r % (64*72);
        int n = rem / 72, kk = rem % 72;
        float v = 0.f;
        if (kk < 64) {
            int w = kc * 64 + kk;
            float s, c; sincospif((float)((n >> 1) * w) / 128.0f, &s, &c);
            v = (n & 1) ? -s : c;
        }
        __nv_bfloat16 h, l; split_bf(v, h, l);
        g_BWh[r] = h; g_BWl[r] = l;
    } else if (seg == 1) {               // irfft basis
        int nh = r / (128*72);
        int rem = r % (128*72);
        int wn = rem / 72, j = rem % 72;
        float v = 0.f;
        if (j < 64) {
            int w = nh * 128 + wn;
            int q = j >> 1;
            float s, c; sincospif((float)(q * w) / 128.0f, &s, &c);
            float alpha = ((q == 0) ? 1.0f : 2.0f) * (1.0f / 256.0f);
            v = (j & 1) ? -alpha * s : alpha * c;
        }
        __nv_bfloat16 h, l; split_bf(v, h, l);
        g_BIh[r] = h; g_BIl[r] = l;
    } else if (seg == 2) {               // fwdH A: TH[sx][h]
        int kc = r / (64*72);
        int rem = r % (64*72);
        int sx = rem / 72, kk = rem % 72;
        float vr = 0.f, vi = 0.f;
        if (kk < 64) {
            int h = kc * 64 + kk;
            int kx = (sx < 32) ? sx : (192 + sx);
            float s, c; sincospif((float)(kx * h) / 128.0f, &s, &c);
            vr = c; vi = -s;
        }
        __nv_bfloat16 h1, l1; split_bf(vr, h1, l1);
        g_THr_h[r] = h1; g_THr_l[r] = l1;
        split_bf(vi, h1, l1);
        g_THi_h[r] = h1; g_THi_l[r] = l1;
    } else if (seg == 3) {               // invH A: conj(TH)^T [h][sx]
        int hh = r / (128*72);
        int rem = r % (128*72);
        int hn = rem / 72, sk = rem % 72;
        float vr = 0.f, vi = 0.f;
        if (sk < 64) {
            int h = hh * 128 + hn;
            int kx = (sk < 32) ? sk : (192 + sk);
            float s, c; sincospif((float)(kx * h) / 128.0f, &s, &c);
            vr = c; vi = s;
        }
        __nv_bfloat16 h1, l1; split_bf(vr, h1, l1);
        g_TIr_h[r] = h1; g_TIr_l[r] = l1;
        split_bf(vi, h1, l1);
        g_TIi_h[r] = h1; g_TIi_l[r] = l1;
    }
}

// ---- K0b: transpose weights [p][kxy] -> [kxy][p] ----
__global__ void __launch_bounds__(256) k_wtrans(const float* __restrict__ w0,
                                                const float* __restrict__ w1,
                                                const float* __restrict__ we0,
                                                const float* __restrict__ we1) {
    __shared__ float2 sm[32][33];
    int bid = blockIdx.x;
    int arr = bid >> 10;
    int tile = bid & 1023;
    int I = tile >> 5, J = tile & 31;
    const float2* src = (const float2*)((arr == 0) ? w0 : (arr == 1) ? w1 : (arr == 2) ? we0 : we1);
    float2* dst = (arr < 2) ? (g_Wt + (size_t)arr * 1024 * 1024)
                            : (g_Wet + (size_t)(arr - 2) * 1024 * 1024);
    int t = threadIdx.x;
    int c = t & 31, rq = t >> 5;
    #pragma unroll
    for (int i = 0; i < 4; i++)
        sm[rq + 8 * i][c] = src[(size_t)(I * 32 + rq + 8 * i) * 1024 + J * 32 + c];
    __syncthreads();
    #pragma unroll
    for (int i = 0; i < 4; i++)
        dst[(size_t)(J * 32 + rq + 8 * i) * 1024 + I * 32 + c] = sm[c][rq + 8 * i];
}

// ============== K1: fwd DFT along W via mma.sync bf16 ==============
#define FW_SMEM 55296
__global__ void __launch_bounds__(256) k_fwdW_m(const float* __restrict__ x) {
    extern __shared__ unsigned char smem[];
    __nv_bfloat16* Ah = (__nv_bfloat16*)(smem);
    __nv_bfloat16* Al = (__nv_bfloat16*)(smem + 18432);
    __nv_bfloat16* Bh = (__nv_bfloat16*)(smem + 36864);
    __nv_bfloat16* Bl = (__nv_bfloat16*)(smem + 46080);
    int tid = threadIdx.x, lane = tid & 31, wid = tid >> 5;
    int g = lane >> 2, t4 = lane & 3;
    size_t rowBase = (size_t)blockIdx.x * 128;
    int m0 = wid * 16;
    float acc[8][4];
    #pragma unroll
    for (int nt = 0; nt < 8; nt++)
        #pragma unroll
        for (int i = 0; i < 4; i++) acc[nt][i] = 0.f;

    const float4* xg = (const float4*)x;
    for (int kc = 0; kc < 4; kc++) {
        __syncthreads();
        #pragma unroll
        for (int i = 0; i < 8; i++) {
            int idx = tid + 256 * i;
            int r = idx >> 4, c4 = idx & 15;
            float4 v = xg[(rowBase + r) * 64 + kc * 16 + c4];
            __nv_bfloat16 h0, h1, h2, h3, l0, l1, l2, l3;
            split_bf(v.x, h0, l0); split_bf(v.y, h1, l1);
            split_bf(v.z, h2, l2); split_bf(v.w, h3, l3);
            *(uint2*)(Ah + r * 72 + c4 * 4) = make_uint2(pack_bf(h0, h1), pack_bf(h2, h3));
            *(uint2*)(Al + r * 72 + c4 * 4) = make_uint2(pack_bf(l0, l1), pack_bf(l2, l3));
        }
        {
            const uint4* sh = ((const uint4*)g_BWh) + kc * 576;
            const uint4* sl = ((const uint4*)g_BWl) + kc * 576;
            uint4* dh = (uint4*)Bh; uint4* dl = (uint4*)Bl;
            for (int i = tid; i < 576; i += 256) { dh[i] = sh[i]; dl[i] = sl[i]; }
        }
        __syncthreads();
        #pragma unroll
        for (int ks = 0; ks < 4; ks++) {
            int aoff = (m0 + g) * 72 + ks * 16 + 2 * t4;
            uint32_t ah[4], al[4];
            ah[0] = *(const uint32_t*)(Ah + aoff);
            ah[1] = *(const uint32_t*)(Ah + aoff + 8 * 72);
            ah[2] = *(const uint32_t*)(Ah + aoff + 8);
            ah[3] = *(const uint32_t*)(Ah + aoff + 8 * 72 + 8);
            al[0] = *(const uint32_t*)(Al + aoff);
            al[1] = *(const uint32_t*)(Al + aoff + 8 * 72);
            al[2] = *(const uint32_t*)(Al + aoff + 8);
            al[3] = *(const uint32_t*)(Al + aoff + 8 * 72 + 8);
            #pragma unroll
            for (int nt = 0; nt < 8; nt++) {
                int boff = (nt * 8 + g) * 72 + ks * 16 + 2 * t4;
                uint32_t bh[2], bl[2];
                bh[0] = *(const uint32_t*)(Bh + boff);
                bh[1] = *(const uint32_t*)(Bh + boff + 8);
                bl[0] = *(const uint32_t*)(Bl + boff);
                bl[1] = *(const uint32_t*)(Bl + boff + 8);
                mma16816(acc[nt], ah, bh);
                mma16816(acc[nt], ah, bl);
                mma16816(acc[nt], al, bh);
            }
        }
    }
    float2* gx = (float2*)g_Xw;
    #pragma unroll
    for (int nt = 0; nt < 8; nt++) {
        int col = nt * 4 + t4;
        gx[(rowBase + m0 + g) * 32 + col]     = make_float2(acc[nt][0], acc[nt][1]);
        gx[(rowBase + m0 + g + 8) * 32 + col] = make_float2(acc[nt][2], acc[nt][3]);
    }
}

// ============== K2: fwd DFT along H via mma.sync (two-real-GEMM complex) ==============
// per (b,ci): C[64 sx][64 col] = TH[64x256] * X[256 h][64 col];  B = X^T staged (pad 258)
#define FH_SMEM 102912
__global__ void __launch_bounds__(256) k_fwdH_m() {
    extern __shared__ unsigned char smem[];
    __nv_bfloat16* Bh  = (__nv_bfloat16*)(smem);
    __nv_bfloat16* Bl  = (__nv_bfloat16*)(smem + 33024);
    __nv_bfloat16* Arh = (__nv_bfloat16*)(smem + 66048);
    __nv_bfloat16* Arl = (__nv_bfloat16*)(smem + 75264);
    __nv_bfloat16* Aih = (__nv_bfloat16*)(smem + 84480);
    __nv_bfloat16* Ail = (__nv_bfloat16*)(smem + 93696);
    int tid = threadIdx.x, lane = tid & 31, wid = tid >> 5;
    int g = lane >> 2, t4 = lane & 3;
    int bci = blockIdx.x;
    int m0 = (wid & 3) * 16, n0 = (wid >> 2) * 32;

    // stage B = X^T: [col(64)][h pad 258] bf16 hi/lo
    {
        const float2* Xp = g_Xw + (size_t)bci * 256 * 32;
        int k = tid & 31, hb = tid >> 5;
        #pragma unroll 8
        for (int j = 0; j < 32; j++) {
            int h = hb + 8 * j;
            float2 v = Xp[h * 32 + k];
            __nv_bfloat16 rh, rl, ih, il;
            split_bf(v.x, rh, rl); split_bf(v.y, ih, il);
            Bh[(2*k)   * 258 + h] = rh;  Bl[(2*k)   * 258 + h] = rl;
            Bh[(2*k+1) * 258 + h] = ih;  Bl[(2*k+1) * 258 + h] = il;
        }
    }
    float accP[4][4], accQ[4][4];
    #pragma unroll
    for (int nt = 0; nt < 4; nt++)
        #pragma unroll
        for (int i = 0; i < 4; i++) { accP[nt][i] = 0.f; accQ[nt][i] = 0.f; }

    for (int kc = 0; kc < 4; kc++) {
        __syncthreads();
        {   // stage A chunk: 64 sx x 72, 4 arrays
            const uint4* s0 = ((const uint4*)g_THr_h) + kc * 576;
            const uint4* s1 = ((const uint4*)g_THr_l) + kc * 576;
            const uint4* s2 = ((const uint4*)g_THi_h) + kc * 576;
            const uint4* s3 = ((const uint4*)g_THi_l) + kc * 576;
            uint4* d0 = (uint4*)Arh; uint4* d1 = (uint4*)Arl;
            uint4* d2 = (uint4*)Aih; uint4* d3 = (uint4*)Ail;
            for (int i = tid; i < 576; i += 256) { d0[i]=s0[i]; d1[i]=s1[i]; d2[i]=s2[i]; d3[i]=s3[i]; }
        }
        __syncthreads();
        #pragma unroll
        for (int ks = 0; ks < 4; ks++) {
            int aoff = (m0 + g) * 72 + ks * 16 + 2 * t4;
            uint32_t arh[4], arl[4], aih[4], ail[4];
            arh[0]=*(const uint32_t*)(Arh+aoff);        arh[1]=*(const uint32_t*)(Arh+aoff+8*72);
            arh[2]=*(const uint32_t*)(Arh+aoff+8);      arh[3]=*(const uint32_t*)(Arh+aoff+8*72+8);
            arl[0]=*(const uint32_t*)(Arl+aoff);        arl[1]=*(const uint32_t*)(Arl+aoff+8*72);
            arl[2]=*(const uint32_t*)(Arl+aoff+8);      arl[3]=*(const uint32_t*)(Arl+aoff+8*72+8);
            aih[0]=*(const uint32_t*)(Aih+aoff);        aih[1]=*(const uint32_t*)(Aih+aoff+8*72);
            aih[2]=*(const uint32_t*)(Aih+aoff+8);      aih[3]=*(const uint32_t*)(Aih+aoff+8*72+8);
            ail[0]=*(const uint32_t*)(Ail+aoff);        ail[1]=*(const uint32_t*)(Ail+aoff+8*72);
            ail[2]=*(const uint32_t*)(Ail+aoff+8);      ail[3]=*(const uint32_t*)(Ail+aoff+8*72+8);
            #pragma unroll
            for (int nt = 0; nt < 4; nt++) {
                int boff = (n0 + nt * 8 + g) * 258 + kc * 64 + ks * 16 + 2 * t4;
                uint32_t bh[2], bl[2];
                bh[0] = *(const uint32_t*)(Bh + boff);
                bh[1] = *(const uint32_t*)(Bh + boff + 8);
                bl[0] = *(const uint32_t*)(Bl + boff);
                bl[1] = *(const uint32_t*)(Bl + boff + 8);
                mma16816(accP[nt], arh, bh);
                mma16816(accP[nt], arh, bl);
                mma16816(accP[nt], arl, bh);
                mma16816(accQ[nt], aih, bh);
                mma16816(accQ[nt], aih, bl);
                mma16816(accQ[nt], ail, bh);
            }
        }
    }
    // combine + write:  out_re = P0 - Q1, out_im = P1 + Q0, scaled 1/256
    const float nrm = 1.0f / 256.0f;
    float2* gx = g_Xf + (size_t)bci * 64 * 32;
    #pragma unroll
    for (int nt = 0; nt < 4; nt++) {
        int col2 = (n0 >> 1) + nt * 4 + t4;
        gx[(m0 + g) * 32 + col2] = make_float2((accP[nt][0] - accQ[nt][1]) * nrm,
                                               (accP[nt][1] + accQ[nt][0]) * nrm);
        gx[(m0 + g + 8) * 32 + col2] = make_float2((accP[nt][2] - accQ[nt][3]) * nrm,
                                                   (accP[nt][3] + accQ[nt][2]) * nrm);
    }
}

// ---- K3: channel mixing ----
__global__ void __launch_bounds__(256) k_mix(const float* __restrict__ fs) {
    __shared__ float2 Ws[1024];
    __shared__ float2 Wes[1024];
    __shared__ float2 Xs[16][32];
    __shared__ float  ssm[16];
    int bid = blockIdx.x;
    int r = bid >> 10, kxy = bid & 1023;
    int kx = kxy >> 5, ky = kxy & 31;
    int sxg = r * 32 + kx;
    const float2* Wp  = g_Wt  + ((size_t)r << 20) + ((size_t)kxy << 10);
    const float2* Wep = g_Wet + ((size_t)r << 20) + ((size_t)kxy << 10);
    int t = threadIdx.x;
    #pragma unroll
    for (int i = 0; i < 4; i++) {
        Ws [t + 256*i] = Wp [t + 256*i];
        Wes[t + 256*i] = Wep[t + 256*i];
    }
    #pragma unroll
    for (int i = 0; i < 2; i++) {
        int p = t + 256*i;
        Xs[p >> 5][p & 31] = g_Xf[((size_t)p * 64 + sxg) * 32 + ky];
    }
    if (t < 16) {
        int idx;
        if (kx < 8 && ky < 8)        idx = 0;
        else if (kx < 16 && ky < 16) idx = (kx < 8) ? 1 : ((ky < 8) ? 2 : 3);
        else                         idx = (kx < 16) ? 4 : ((ky < 16) ? 5 : 6);
        ssm[t] = fs[t * 7 + idx];
    }
    __syncthreads();
    int co = t & 31, bh = t >> 5;
    float sb0 = ssm[bh], sb1 = ssm[bh + 8];
    float a0x = 0.f, a0y = 0.f, a1x = 0.f, a1y = 0.f;
    #pragma unroll 8
    for (int ci = 0; ci < 32; ci++) {
        float2 w  = Ws [ci * 32 + co];
        float2 we = Wes[ci * 32 + co];
        float2 x0 = Xs[bh][ci];
        float2 x1 = Xs[bh + 8][ci];
        float wr0 = fmaf(sb0, we.x, w.x), wi0 = fmaf(sb0, we.y, w.y);
        float wr1 = fmaf(sb1, we.x, w.x), wi1 = fmaf(sb1, we.y, w.y);
        a0x = fmaf(x0.x, wr0, fmaf(-x0.y, wi0, a0x));
        a0y = fmaf(x0.x, wi0, fmaf( x0.y, wr0, a0y));
        a1x = fmaf(x1.x, wr1, fmaf(-x1.y, wi1, a1x));
        a1y = fmaf(x1.x, wi1, fmaf( x1.y, wr1, a1y));
    }
    g_Of[(((size_t)bh       * 32 + co) * 64 + sxg) * 32 + ky] = make_float2(a0x, a0y);
    g_Of[(((size_t)(bh + 8) * 32 + co) * 64 + sxg) * 32 + ky] = make_float2(a1x, a1y);
}

// ============== K4: inverse DFT along H via mma.sync ==============
// per (b,co, h-half): C[128 h][64 col] = conj(TH)^T[128x64] * O[64 sx][64 col]; B = O^T (pad 66)
#define IH_SMEM 90624
__global__ void __launch_bounds__(256) k_invH_m() {
    extern __shared__ unsigned char smem[];
    __nv_bfloat16* Bh  = (__nv_bfloat16*)(smem);
    __nv_bfloat16* Bl  = (__nv_bfloat16*)(smem + 8448);
    __nv_bfloat16* Arh = (__nv_bfloat16*)(smem + 16896);
    __nv_bfloat16* Arl = (__nv_bfloat16*)(smem + 35328);
    __nv_bfloat16* Aih = (__nv_bfloat16*)(smem + 53760);
    __nv_bfloat16* Ail = (__nv_bfloat16*)(smem + 72192);
    int tid = threadIdx.x, lane = tid & 31, wid = tid >> 5;
    int g = lane >> 2, t4 = lane & 3;
    int bco = blockIdx.x >> 1, hh = blockIdx.x & 1;
    int m0 = wid * 16;

    // stage B = O^T: [col(64)][sx pad 66]
    {
        const float2* Op = g_Of + (size_t)bco * 64 * 32;
        #pragma unroll
        for (int i = 0; i < 8; i++) {
            int idx = tid + 256 * i;
            int sx = idx >> 5, k = idx & 31;
            float2 v = Op[idx];
            __nv_bfloat16 rh, rl, ih, il;
            split_bf(v.x, rh, rl); split_bf(v.y, ih, il);
            Bh[(2*k)   * 66 + sx] = rh;  Bl[(2*k)   * 66 + sx] = rl;
            Bh[(2*k+1) * 66 + sx] = ih;  Bl[(2*k+1) * 66 + sx] = il;
        }
    }
    {   // stage A: [128 h][72 sx] x4 arrays
        const uint4* s0 = ((const uint4*)g_TIr_h) + hh * 1152;
        const uint4* s1 = ((const uint4*)g_TIr_l) + hh * 1152;
        const uint4* s2 = ((const uint4*)g_TIi_h) + hh * 1152;
        const uint4* s3 = ((const uint4*)g_TIi_l) + hh * 1152;
        uint4* d0 = (uint4*)Arh; uint4* d1 = (uint4*)Arl;
        uint4* d2 = (uint4*)Aih; uint4* d3 = (uint4*)Ail;
        for (int i = tid; i < 1152; i += 256) { d0[i]=s0[i]; d1[i]=s1[i]; d2[i]=s2[i]; d3[i]=s3[i]; }
    }
    __syncthreads();

    float accP[8][4], accQ[8][4];
    #pragma unroll
    for (int nt = 0; nt < 8; nt++)
        #pragma unroll
        for (int i = 0; i < 4; i++) { accP[nt][i] = 0.f; accQ[nt][i] = 0.f; }

    #pragma unroll
    for (int ks = 0; ks < 4; ks++) {
        int aoff = (m0 + g) * 72 + ks * 16 + 2 * t4;
        uint32_t arh[4], arl[4], aih[4], ail[4];
        arh[0]=*(const uint32_t*)(Arh+aoff);        arh[1]=*(const uint32_t*)(Arh+aoff+8*72);
        arh[2]=*(const uint32_t*)(Arh+aoff+8);      arh[3]=*(const uint32_t*)(Arh+aoff+8*72+8);
        arl[0]=*(const uint32_t*)(Arl+aoff);        arl[1]=*(const uint32_t*)(Arl+aoff+8*72);
        arl[2]=*(const uint32_t*)(Arl+aoff+8);      arl[3]=*(const uint32_t*)(Arl+aoff+8*72+8);
        aih[0]=*(const uint32_t*)(Aih+aoff);        aih[1]=*(const uint32_t*)(Aih+aoff+8*72);
        aih[2]=*(const uint32_t*)(Aih+aoff+8);      aih[3]=*(const uint32_t*)(Aih+aoff+8*72+8);
        ail[0]=*(const uint32_t*)(Ail+aoff);        ail[1]=*(const uint32_t*)(Ail+aoff+8*72);
        ail[2]=*(const uint32_t*)(Ail+aoff+8);      ail[3]=*(const uint32_t*)(Ail+aoff+8*72+8);
        #pragma unroll
        for (int nt = 0; nt < 8; nt++) {
            int boff = (nt * 8 + g) * 66 + ks * 16 + 2 * t4;
            uint32_t bh[2], bl[2];
            bh[0] = *(const uint32_t*)(Bh + boff);
            bh[1] = *(const uint32_t*)(Bh + boff + 8);
            bl[0] = *(const uint32_t*)(Bl + boff);
            bl[1] = *(const uint32_t*)(Bl + boff + 8);
            mma16816(accP[nt], arh, bh);
            mma16816(accP[nt], arh, bl);
            mma16816(accP[nt], arl, bh);
            mma16816(accQ[nt], aih, bh);
            mma16816(accQ[nt], aih, bl);
            mma16816(accQ[nt], ail, bh);
        }
    }
    float2* gt = g_Tmp + (size_t)bco * 256 * 32 + (size_t)hh * 128 * 32;
    #pragma unroll
    for (int nt = 0; nt < 8; nt++) {
        int col2 = nt * 4 + t4;
        gt[(m0 + g) * 32 + col2] = make_float2(accP[nt][0] - accQ[nt][1],
                                               accP[nt][1] + accQ[nt][0]);
        gt[(m0 + g + 8) * 32 + col2] = make_float2(accP[nt][2] - accQ[nt][3],
                                                   accP[nt][3] + accQ[nt][2]);
    }
}

// ============== K5: inverse real DFT along W via mma.sync ==============
#define IR_SMEM 73728
__global__ void __launch_bounds__(256) k_irfftW_m(float* __restrict__ out) {
    extern __shared__ unsigned char smem[];
    __nv_bfloat16* Ah = (__nv_bfloat16*)(smem);
    __nv_bfloat16* Al = (__nv_bfloat16*)(smem + 18432);
    __nv_bfloat16* Bh = (__nv_bfloat16*)(smem + 36864);
    __nv_bfloat16* Bl = (__nv_bfloat16*)(smem + 55296);
    int tid = threadIdx.x, lane = tid & 31, wid = tid >> 5;
    int g = lane >> 2, t4 = lane & 3;
    int rg = blockIdx.x >> 1, nh = blockIdx.x & 1;
    size_t rowBase = (size_t)rg * 128;

    const float4* ag = (const float4*)g_Tmp;
    #pragma unroll
    for (int i = 0; i < 8; i++) {
        int idx = tid + 256 * i;
        int r = idx >> 4, c4 = idx & 15;
        float4 v = ag[(rowBase + r) * 16 + c4];
        __nv_bfloat16 h0, h1, h2, h3, l0, l1, l2, l3;
        split_bf(v.x, h0, l0); split_bf(v.y, h1, l1);
        split_bf(v.z, h2, l2); split_bf(v.w, h3, l3);
        *(uint2*)(Ah + r * 72 + c4 * 4) = make_uint2(pack_bf(h0, h1), pack_bf(h2, h3));
        *(uint2*)(Al + r * 72 + c4 * 4) = make_uint2(pack_bf(l0, l1), pack_bf(l2, l3));
    }
    {
        const uint4* sh = ((const uint4*)g_BIh) + nh * 1152;
        const uint4* sl = ((const uint4*)g_BIl) + nh * 1152;
        uint4* dh = (uint4*)Bh; uint4* dl = (uint4*)Bl;
        for (int i = tid; i < 1152; i += 256) { dh[i] = sh[i]; dl[i] = sl[i]; }
    }
    __syncthreads();

    int m0 = (wid >> 1) * 32;
    int n0 = (wid & 1) * 64;
    float acc[2][8][4];
    #pragma unroll
    for (int mt = 0; mt < 2; mt++)
        #pragma unroll
        for (int nt = 0; nt < 8; nt++)
            #pragma unroll
            for (int i = 0; i < 4; i++) acc[mt][nt][i] = 0.f;

    #pragma unroll
    for (int ks = 0; ks < 4; ks++) {
        uint32_t ah[2][4], al[2][4];
        #pragma unroll
        for (int mt = 0; mt < 2; mt++) {
            int aoff = (m0 + mt * 16 + g) * 72 + ks * 16 + 2 * t4;
            ah[mt][0] = *(const uint32_t*)(Ah + aoff);
            ah[mt][1] = *(const uint32_t*)(Ah + aoff + 8 * 72);
            ah[mt][2] = *(const uint32_t*)(Ah + aoff + 8);
            ah[mt][3] = *(const uint32_t*)(Ah + aoff + 8 * 72 + 8);
            al[mt][0] = *(const uint32_t*)(Al + aoff);
            al[mt][1] = *(const uint32_t*)(Al + aoff + 8 * 72);
            al[mt][2] = *(const uint32_t*)(Al + aoff + 8);
            al[mt][3] = *(const uint32_t*)(Al + aoff + 8 * 72 + 8);
        }
        #pragma unroll
        for (int nt = 0; nt < 8; nt++) {
            int boff = (n0 + nt * 8 + g) * 72 + ks * 16 + 2 * t4;
            uint32_t bh[2], bl[2];
            bh[0] = *(const uint32_t*)(Bh + boff);
            bh[1] = *(const uint32_t*)(Bh + boff + 8);
            bl[0] = *(const uint32_t*)(Bl + boff);
            bl[1] = *(const uint32_t*)(Bl + boff + 8);
            #pragma unroll
            for (int mt = 0; mt < 2; mt++) {
                mma16816(acc[mt][nt], ah[mt], bh);
                mma16816(acc[mt][nt], ah[mt], bl);
                mma16816(acc[mt][nt], al[mt], bh);
            }
        }
    }
    #pragma unroll
    for (int mt = 0; mt < 2; mt++) {
        size_t r0 = rowBase + m0 + mt * 16 + g;
        #pragma unroll
        for (int nt = 0; nt < 8; nt++) {
            int col = nh * 128 + n0 + nt * 8 + 2 * t4;
            *(float2*)(out + r0 * 256 + col)       = make_float2(acc[mt][nt][0], acc[mt][nt][1]);
            *(float2*)(out + (r0 + 8) * 256 + col) = make_float2(acc[mt][nt][2], acc[mt][nt][3]);
        }
    }
}

extern "C" void kernel_launch(void* const* d_in, const int* in_sizes, int n_in,
                              void* d_out, int out_size) {
    const float* x   = (const float*)d_in[0];
    const float* fs  = (const float*)d_in[1];
    const float* w0  = (const float*)d_in[2];
    const float* w1  = (const float*)d_in[3];
    const float* we0 = (const float*)d_in[4];
    const float* we1 = (const float*)d_in[5];
    float* out = (float*)d_out;

    cudaFuncSetAttribute(k_fwdW_m,   cudaFuncAttributeMaxDynamicSharedMemorySize, FW_SMEM);
    cudaFuncSetAttribute(k_fwdH_m,   cudaFuncAttributeMaxDynamicSharedMemorySize, FH_SMEM);
    cudaFuncSetAttribute(k_invH_m,   cudaFuncAttributeMaxDynamicSharedMemorySize, IH_SMEM);
    cudaFuncSetAttribute(k_irfftW_m, cudaFuncAttributeMaxDynamicSharedMemorySize, IR_SMEM);

    k_init<<<288, 256>>>();
    k_wtrans<<<4096, 256>>>(w0, w1, we0, we1);
    k_fwdW_m<<<RTOT / 128, 256, FW_SMEM>>>(x);        // 1024 CTAs
    k_fwdH_m<<<Bsz * CIn, 256, FH_SMEM>>>();          // 512 CTAs
    k_mix<<<2 * 1024, 256>>>(fs);
    k_invH_m<<<Bsz * COn * 2, 256, IH_SMEM>>>();      // 1024 CTAs
    k_irfftW_m<<<RTOT / 64, 256, IR_SMEM>>>(out);     // 2048 CTAs
}

// round 8
// speedup vs baseline: 1.0677x; 1.0677x over previous
#include <cuda_runtime.h>
#include <cuda_bf16.h>
#include <math.h>
#include <stdint.h>

// Problem constants
#define Bsz 16
#define CIn 32
#define COn 32
#define Hn  256
#define Wn  256
#define KM  32
#define SXn 64
#define RTOT (Bsz*CIn*Hn)   // 131072 rows

// ============================ tables / scratch ============================
// fwdW basis  [kc(4)][n(64)][72pad]  bf16 hi/lo
__device__ __align__(16) __nv_bfloat16 g_BWh[4*64*72], g_BWl[4*64*72];
// irfft basis [nh(2)][wn(128)][72pad] bf16 hi/lo
__device__ __align__(16) __nv_bfloat16 g_BIh[2*128*72], g_BIl[2*128*72];
// fwdH A tables: TH[sx][h] chunked [kc(4)][sx(64)][72pad]; re=cos, im=-sin
__device__ __align__(16) __nv_bfloat16 g_THr_h[4*64*72], g_THr_l[4*64*72];
__device__ __align__(16) __nv_bfloat16 g_THi_h[4*64*72], g_THi_l[4*64*72];
// invH A tables: conj(TH)^T flat [h(256)][72pad sx]; re=cos, im=+sin
__device__ __align__(16) __nv_bfloat16 g_TIr_h[2*128*72], g_TIr_l[2*128*72];
__device__ __align__(16) __nv_bfloat16 g_TIi_h[2*128*72], g_TIi_l[2*128*72];

__device__ float2 g_XwT[(size_t)Bsz*CIn*KM*Hn];   // fwdW out, TRANSPOSED [bci][c(32)][h(256)]
__device__ float2 g_Xf[(size_t)Bsz*CIn*SXn*KM];   // fwdH out [bci][sx][ky]
__device__ float2 g_OfT[(size_t)Bsz*COn*KM*SXn];  // mix out, TRANSPOSED [bco][ky(32)][sx(64)]
__device__ float2 g_Tmp[(size_t)Bsz*COn*Hn*KM];   // invH out [bco*256+h][ky]
__device__ float2 g_Wt [2*1024*1024];
__device__ float2 g_Wet[2*1024*1024];

// ============================ helpers ============================
__device__ __forceinline__ uint32_t pack_bf(__nv_bfloat16 a, __nv_bfloat16 b) {
    return (uint32_t)__bfloat16_as_ushort(a) | ((uint32_t)__bfloat16_as_ushort(b) << 16);
}
__device__ __forceinline__ void split_bf(float v, __nv_bfloat16& h, __nv_bfloat16& l) {
    h = __float2bfloat16(v);
    l = __float2bfloat16(v - __bfloat162float(h));
}
__device__ __forceinline__ void mma16816(float* c, const uint32_t* a, const uint32_t* b) {
    asm volatile("mma.sync.aligned.m16n8k16.row.col.f32.bf16.bf16.f32 "
        "{%0,%1,%2,%3}, {%4,%5,%6,%7}, {%8,%9}, {%0,%1,%2,%3};"
        : "+f"(c[0]), "+f"(c[1]), "+f"(c[2]), "+f"(c[3])
        : "r"(a[0]), "r"(a[1]), "r"(a[2]), "r"(a[3]), "r"(b[0]), "r"(b[1]));
}

#define SEG 18432   // 4*64*72 == 2*128*72

__global__ void k_init() {
    int t = blockIdx.x * blockDim.x + threadIdx.x;
    int seg = t / SEG, r = t % SEG;
    if (seg == 0) {                      // fwdW basis
        int kc = r / (64*72);
        int rem = r % (64*72);
        int n = rem / 72, kk = rem % 72;
        float v = 0.f;
        if (kk < 64) {
            int w = kc * 64 + kk;
            float s, c; sincospif((float)((n >> 1) * w) / 128.0f, &s, &c);
            v = (n & 1) ? -s : c;
        }
        __nv_bfloat16 h, l; split_bf(v, h, l);
        g_BWh[r] = h; g_BWl[r] = l;
    } else if (seg == 1) {               // irfft basis
        int nh = r / (128*72);
        int rem = r % (128*72);
        int wn = rem / 72, j = rem % 72;
        float v = 0.f;
        if (j < 64) {
            int w = nh * 128 + wn;
            int q = j >> 1;
            float s, c; sincospif((float)(q * w) / 128.0f, &s, &c);
            float alpha = ((q == 0) ? 1.0f : 2.0f) * (1.0f / 256.0f);
            v = (j & 1) ? -alpha * s : alpha * c;
        }
        __nv_bfloat16 h, l; split_bf(v, h, l);
        g_BIh[r] = h; g_BIl[r] = l;
    } else if (seg == 2) {               // fwdH A: TH[sx][h]
        int kc = r / (64*72);
        int rem = r % (64*72);
        int sx = rem / 72, kk = rem % 72;
        float vr = 0.f, vi = 0.f;
        if (kk < 64) {
            int h = kc * 64 + kk;
            int kx = (sx < 32) ? sx : (192 + sx);
            float s, c; sincospif((float)(kx * h) / 128.0f, &s, &c);
            vr = c; vi = -s;
        }
        __nv_bfloat16 h1, l1; split_bf(vr, h1, l1);
        g_THr_h[r] = h1; g_THr_l[r] = l1;
        split_bf(vi, h1, l1);
        g_THi_h[r] = h1; g_THi_l[r] = l1;
    } else if (seg == 3) {               // invH A: conj(TH)^T flat [h][sx]
        int hn = r / 72, sk = r % 72;    // hn = 0..255
        float vr = 0.f, vi = 0.f;
        if (sk < 64) {
            int kx = (sk < 32) ? sk : (192 + sk);
            float s, c; sincospif((float)(kx * hn) / 128.0f, &s, &c);
            vr = c; vi = s;
        }
        __nv_bfloat16 h1, l1; split_bf(vr, h1, l1);
        g_TIr_h[r] = h1; g_TIr_l[r] = l1;
        split_bf(vi, h1, l1);
        g_TIi_h[r] = h1; g_TIi_l[r] = l1;
    }
}

// ---- K0b: transpose weights [p][kxy] -> [kxy][p] ----
__global__ void __launch_bounds__(256) k_wtrans(const float* __restrict__ w0,
                                                const float* __restrict__ w1,
                                                const float* __restrict__ we0,
                                                const float* __restrict__ we1) {
    __shared__ float2 sm[32][33];
    int bid = blockIdx.x;
    int arr = bid >> 10;
    int tile = bid & 1023;
    int I = tile >> 5, J = tile & 31;
    const float2* src = (const float2*)((arr == 0) ? w0 : (arr == 1) ? w1 : (arr == 2) ? we0 : we1);
    float2* dst = (arr < 2) ? (g_Wt + (size_t)arr * 1024 * 1024)
                            : (g_Wet + (size_t)(arr - 2) * 1024 * 1024);
    int t = threadIdx.x;
    int c = t & 31, rq = t >> 5;
    #pragma unroll
    for (int i = 0; i < 4; i++)
        sm[rq + 8 * i][c] = src[(size_t)(I * 32 + rq + 8 * i) * 1024 + J * 32 + c];
    __syncthreads();
    #pragma unroll
    for (int i = 0; i < 4; i++)
        dst[(size_t)(J * 32 + rq + 8 * i) * 1024 + I * 32 + c] = sm[c][rq + 8 * i];
}

// ============== K1: fwd DFT along W via mma.sync; output TRANSPOSED per image ==============
#define FW_SMEM 55296
__global__ void __launch_bounds__(256) k_fwdW_m(const float* __restrict__ x) {
    extern __shared__ unsigned char smem[];
    __nv_bfloat16* Ah = (__nv_bfloat16*)(smem);
    __nv_bfloat16* Al = (__nv_bfloat16*)(smem + 18432);
    __nv_bfloat16* Bh = (__nv_bfloat16*)(smem + 36864);
    __nv_bfloat16* Bl = (__nv_bfloat16*)(smem + 46080);
    int tid = threadIdx.x, lane = tid & 31, wid = tid >> 5;
    int g = lane >> 2, t4 = lane & 3;
    size_t rowBase = (size_t)blockIdx.x * 128;
    int m0 = wid * 16;
    float acc[8][4];
    #pragma unroll
    for (int nt = 0; nt < 8; nt++)
        #pragma unroll
        for (int i = 0; i < 4; i++) acc[nt][i] = 0.f;

    const float4* xg = (const float4*)x;
    for (int kc = 0; kc < 4; kc++) {
        __syncthreads();
        #pragma unroll
        for (int i = 0; i < 8; i++) {
            int idx = tid + 256 * i;
            int r = idx >> 4, c4 = idx & 15;
            float4 v = xg[(rowBase + r) * 64 + kc * 16 + c4];
            __nv_bfloat16 h0, h1, h2, h3, l0, l1, l2, l3;
            split_bf(v.x, h0, l0); split_bf(v.y, h1, l1);
            split_bf(v.z, h2, l2); split_bf(v.w, h3, l3);
            *(uint2*)(Ah + r * 72 + c4 * 4) = make_uint2(pack_bf(h0, h1), pack_bf(h2, h3));
            *(uint2*)(Al + r * 72 + c4 * 4) = make_uint2(pack_bf(l0, l1), pack_bf(l2, l3));
        }
        {
            const uint4* sh = ((const uint4*)g_BWh) + kc * 576;
            const uint4* sl = ((const uint4*)g_BWl) + kc * 576;
            uint4* dh = (uint4*)Bh; uint4* dl = (uint4*)Bl;
            for (int i = tid; i < 576; i += 256) { dh[i] = sh[i]; dl[i] = sl[i]; }
        }
        __syncthreads();
        #pragma unroll
        for (int ks = 0; ks < 4; ks++) {
            int aoff = (m0 + g) * 72 + ks * 16 + 2 * t4;
            uint32_t ah[4], al[4];
            ah[0] = *(const uint32_t*)(Ah + aoff);
            ah[1] = *(const uint32_t*)(Ah + aoff + 8 * 72);
            ah[2] = *(const uint32_t*)(Ah + aoff + 8);
            ah[3] = *(const uint32_t*)(Ah + aoff + 8 * 72 + 8);
            al[0] = *(const uint32_t*)(Al + aoff);
            al[1] = *(const uint32_t*)(Al + aoff + 8 * 72);
            al[2] = *(const uint32_t*)(Al + aoff + 8);
            al[3] = *(const uint32_t*)(Al + aoff + 8 * 72 + 8);
            #pragma unroll
            for (int nt = 0; nt < 8; nt++) {
                int boff = (nt * 8 + g) * 72 + ks * 16 + 2 * t4;
                uint32_t bh[2], bl[2];
                bh[0] = *(const uint32_t*)(Bh + boff);
                bh[1] = *(const uint32_t*)(Bh + boff + 8);
                bl[0] = *(const uint32_t*)(Bl + boff);
                bl[1] = *(const uint32_t*)(Bl + boff + 8);
                mma16816(acc[nt], ah, bh);
                mma16816(acc[nt], ah, bl);
                mma16816(acc[nt], al, bh);
            }
        }
    }
    // transpose C through smem -> g_XwT[bci][c][h]
    __syncthreads();
    float2* Cs = (float2*)smem;           // [c(32)][r pad 132]
    #pragma unroll
    for (int nt = 0; nt < 8; nt++) {
        int c = nt * 4 + t4;
        Cs[c * 132 + m0 + g]     = make_float2(acc[nt][0], acc[nt][1]);
        Cs[c * 132 + m0 + g + 8] = make_float2(acc[nt][2], acc[nt][3]);
    }
    __syncthreads();
    int bci = blockIdx.x >> 1, hh = blockIdx.x & 1;
    #pragma unroll
    for (int i = 0; i < 16; i++) {
        int idx = tid + 256 * i;
        int c = idx >> 7, r = idx & 127;
        g_XwT[((size_t)bci * 32 + c) * 256 + hh * 128 + r] = Cs[c * 132 + r];
    }
}

// ============== K2: fwd DFT along H via mma.sync; conflict-free staging ==============
// grid = (bci, nh): C[64 sx][32 real cols] = TH[64x256] * Xslice[256][32]
#define FH_SMEM 70656
__global__ void __launch_bounds__(256) k_fwdH_m() {
    extern __shared__ unsigned char smem[];
    __nv_bfloat16* Bh  = (__nv_bfloat16*)(smem);            // [32][264]
    __nv_bfloat16* Bl  = (__nv_bfloat16*)(smem + 16896);
    __nv_bfloat16* Arh = (__nv_bfloat16*)(smem + 33792);    // [64][72]
    __nv_bfloat16* Arl = (__nv_bfloat16*)(smem + 43008);
    __nv_bfloat16* Aih = (__nv_bfloat16*)(smem + 52224);
    __nv_bfloat16* Ail = (__nv_bfloat16*)(smem + 61440);
    int tid = threadIdx.x, lane = tid & 31, wid = tid >> 5;
    int g = lane >> 2, t4 = lane & 3;
    int bci = blockIdx.x >> 1, nh = blockIdx.x & 1;
    int m0 = (wid & 3) * 16, n0 = (wid >> 2) * 16;

    // stage B: 16 complex cols x 256 h; coalesced loads, conflict-free stores
    {
        const float2* Xp = g_XwT + ((size_t)bci * 32 + nh * 16) * 256;
        #pragma unroll
        for (int i = 0; i < 16; i++) {
            int idx = tid + 256 * i;
            int cl = idx >> 8, h = idx & 255;
            float2 v = Xp[idx];
            __nv_bfloat16 rh, rl, ih, il;
            split_bf(v.x, rh, rl); split_bf(v.y, ih, il);
            Bh[(2*cl)   * 264 + h] = rh;  Bl[(2*cl)   * 264 + h] = rl;
            Bh[(2*cl+1) * 264 + h] = ih;  Bl[(2*cl+1) * 264 + h] = il;
        }
    }
    float accP[2][4], accQ[2][4];
    #pragma unroll
    for (int nt = 0; nt < 2; nt++)
        #pragma unroll
        for (int i = 0; i < 4; i++) { accP[nt][i] = 0.f; accQ[nt][i] = 0.f; }

    for (int kc = 0; kc < 4; kc++) {
        __syncthreads();
        {   // stage A chunk: 64 sx x 72, 4 arrays (contiguous copies)
            const uint4* s0 = ((const uint4*)g_THr_h) + kc * 576;
            const uint4* s1 = ((const uint4*)g_THr_l) + kc * 576;
            const uint4* s2 = ((const uint4*)g_THi_h) + kc * 576;
            const uint4* s3 = ((const uint4*)g_THi_l) + kc * 576;
            uint4* d0 = (uint4*)Arh; uint4* d1 = (uint4*)Arl;
            uint4* d2 = (uint4*)Aih; uint4* d3 = (uint4*)Ail;
            for (int i = tid; i < 576; i += 256) { d0[i]=s0[i]; d1[i]=s1[i]; d2[i]=s2[i]; d3[i]=s3[i]; }
        }
        __syncthreads();
        #pragma unroll
        for (int ks = 0; ks < 4; ks++) {
            int aoff = (m0 + g) * 72 + ks * 16 + 2 * t4;
            uint32_t arh[4], arl[4], aih[4], ail[4];
            arh[0]=*(const uint32_t*)(Arh+aoff);        arh[1]=*(const uint32_t*)(Arh+aoff+8*72);
            arh[2]=*(const uint32_t*)(Arh+aoff+8);      arh[3]=*(const uint32_t*)(Arh+aoff+8*72+8);
            arl[0]=*(const uint32_t*)(Arl+aoff);        arl[1]=*(const uint32_t*)(Arl+aoff+8*72);
            arl[2]=*(const uint32_t*)(Arl+aoff+8);      arl[3]=*(const uint32_t*)(Arl+aoff+8*72+8);
            aih[0]=*(const uint32_t*)(Aih+aoff);        aih[1]=*(const uint32_t*)(Aih+aoff+8*72);
            aih[2]=*(const uint32_t*)(Aih+aoff+8);      aih[3]=*(const uint32_t*)(Aih+aoff+8*72+8);
            ail[0]=*(const uint32_t*)(Ail+aoff);        ail[1]=*(const uint32_t*)(Ail+aoff+8*72);
            ail[2]=*(const uint32_t*)(Ail+aoff+8);      ail[3]=*(const uint32_t*)(Ail+aoff+8*72+8);
            #pragma unroll
            for (int nt = 0; nt < 2; nt++) {
                int boff = (n0 + nt * 8 + g) * 264 + kc * 64 + ks * 16 + 2 * t4;
                uint32_t bh[2], bl[2];
                bh[0] = *(const uint32_t*)(Bh + boff);
                bh[1] = *(const uint32_t*)(Bh + boff + 8);
                bl[0] = *(const uint32_t*)(Bl + boff);
                bl[1] = *(const uint32_t*)(Bl + boff + 8);
                mma16816(accP[nt], arh, bh);
                mma16816(accP[nt], arh, bl);
                mma16816(accP[nt], arl, bh);
                mma16816(accQ[nt], aih, bh);
                mma16816(accQ[nt], aih, bl);
                mma16816(accQ[nt], ail, bh);
            }
        }
    }
    const float nrm = 1.0f / 256.0f;
    float2* gx = g_Xf + (size_t)bci * 64 * 32;
    #pragma unroll
    for (int nt = 0; nt < 2; nt++) {
        int col2 = nh * 16 + (n0 >> 1) + nt * 4 + t4;
        gx[(m0 + g) * 32 + col2] = make_float2((accP[nt][0] - accQ[nt][1]) * nrm,
                                               (accP[nt][1] + accQ[nt][0]) * nrm);
        gx[(m0 + g + 8) * 32 + col2] = make_float2((accP[nt][2] - accQ[nt][3]) * nrm,
                                                   (accP[nt][3] + accQ[nt][2]) * nrm);
    }
}

// ---- K3: channel mixing; writes TRANSPOSED g_OfT[bco][ky][sx] ----
__global__ void __launch_bounds__(256) k_mix(const float* __restrict__ fs) {
    __shared__ float2 Ws[1024];
    __shared__ float2 Wes[1024];
    __shared__ float2 Xs[16][32];
    __shared__ float  ssm[16];
    int bid = blockIdx.x;
    int r = bid >> 10, kxy = bid & 1023;
    int kx = kxy >> 5, ky = kxy & 31;
    int sxg = r * 32 + kx;
    const float2* Wp  = g_Wt  + ((size_t)r << 20) + ((size_t)kxy << 10);
    const float2* Wep = g_Wet + ((size_t)r << 20) + ((size_t)kxy << 10);
    int t = threadIdx.x;
    #pragma unroll
    for (int i = 0; i < 4; i++) {
        Ws [t + 256*i] = Wp [t + 256*i];
        Wes[t + 256*i] = Wep[t + 256*i];
    }
    #pragma unroll
    for (int i = 0; i < 2; i++) {
        int p = t + 256*i;
        Xs[p >> 5][p & 31] = g_Xf[((size_t)p * 64 + sxg) * 32 + ky];
    }
    if (t < 16) {
        int idx;
        if (kx < 8 && ky < 8)        idx = 0;
        else if (kx < 16 && ky < 16) idx = (kx < 8) ? 1 : ((ky < 8) ? 2 : 3);
        else                         idx = (kx < 16) ? 4 : ((ky < 16) ? 5 : 6);
        ssm[t] = fs[t * 7 + idx];
    }
    __syncthreads();
    int co = t & 31, bh = t >> 5;
    float sb0 = ssm[bh], sb1 = ssm[bh + 8];
    float a0x = 0.f, a0y = 0.f, a1x = 0.f, a1y = 0.f;
    #pragma unroll 8
    for (int ci = 0; ci < 32; ci++) {
        float2 w  = Ws [ci * 32 + co];
        float2 we = Wes[ci * 32 + co];
        float2 x0 = Xs[bh][ci];
        float2 x1 = Xs[bh + 8][ci];
        float wr0 = fmaf(sb0, we.x, w.x), wi0 = fmaf(sb0, we.y, w.y);
        float wr1 = fmaf(sb1, we.x, w.x), wi1 = fmaf(sb1, we.y, w.y);
        a0x = fmaf(x0.x, wr0, fmaf(-x0.y, wi0, a0x));
        a0y = fmaf(x0.x, wi0, fmaf( x0.y, wr0, a0y));
        a1x = fmaf(x1.x, wr1, fmaf(-x1.y, wi1, a1x));
        a1y = fmaf(x1.x, wi1, fmaf( x1.y, wr1, a1y));
    }
    g_OfT[(((size_t)bh       * 32 + co) * 32 + ky) * 64 + sxg] = make_float2(a0x, a0y);
    g_OfT[(((size_t)(bh + 8) * 32 + co) * 32 + ky) * 64 + sxg] = make_float2(a1x, a1y);
}

// ============== K4: inverse DFT along H via mma.sync; conflict-free staging ==============
// grid = (bco, hq): C[64 h][64 real ky cols] = conj(TH)^T[64x64] * O^T[64x64]
#define IH_SMEM 55296
__global__ void __launch_bounds__(256) k_invH_m() {
    extern __shared__ unsigned char smem[];
    __nv_bfloat16* Bh  = (__nv_bfloat16*)(smem);            // [64][72]
    __nv_bfloat16* Bl  = (__nv_bfloat16*)(smem + 9216);
    __nv_bfloat16* Arh = (__nv_bfloat16*)(smem + 18432);    // [64][72]
    __nv_bfloat16* Arl = (__nv_bfloat16*)(smem + 27648);
    __nv_bfloat16* Aih = (__nv_bfloat16*)(smem + 36864);
    __nv_bfloat16* Ail = (__nv_bfloat16*)(smem + 46080);
    int tid = threadIdx.x, lane = tid & 31, wid = tid >> 5;
    int g = lane >> 2, t4 = lane & 3;
    int bco = blockIdx.x >> 2, hq = blockIdx.x & 3;
    int m0 = (wid & 3) * 16, n0 = (wid >> 2) * 32;

    // stage B = O^T slice: [64 real ky rows][72 pad sx], conflict-free
    {
        const float2* Op = g_OfT + (size_t)bco * 32 * 64;
        #pragma unroll
        for (int i = 0; i < 8; i++) {
            int idx = tid + 256 * i;
            int ky = idx >> 6, sx = idx & 63;
            float2 v = Op[idx];
            __nv_bfloat16 rh, rl, ih, il;
            split_bf(v.x, rh, rl); split_bf(v.y, ih, il);
            Bh[(2*ky)   * 72 + sx] = rh;  Bl[(2*ky)   * 72 + sx] = rl;
            Bh[(2*ky+1) * 72 + sx] = ih;  Bl[(2*ky+1) * 72 + sx] = il;
        }
    }
    {   // stage A: rows hq*64..hq*64+63, 4 arrays
        const uint4* s0 = ((const uint4*)g_TIr_h) + hq * 576;
        const uint4* s1 = ((const uint4*)g_TIr_l) + hq * 576;
        const uint4* s2 = ((const uint4*)g_TIi_h) + hq * 576;
        const uint4* s3 = ((const uint4*)g_TIi_l) + hq * 576;
        uint4* d0 = (uint4*)Arh; uint4* d1 = (uint4*)Arl;
        uint4* d2 = (uint4*)Aih; uint4* d3 = (uint4*)Ail;
        for (int i = tid; i < 576; i += 256) { d0[i]=s0[i]; d1[i]=s1[i]; d2[i]=s2[i]; d3[i]=s3[i]; }
    }
    __syncthreads();

    float accP[4][4], accQ[4][4];
    #pragma unroll
    for (int nt = 0; nt < 4; nt++)
        #pragma unroll
        for (int i = 0; i < 4; i++) { accP[nt][i] = 0.f; accQ[nt][i] = 0.f; }

    #pragma unroll
    for (int ks = 0; ks < 4; ks++) {
        int aoff = (m0 + g) * 72 + ks * 16 + 2 * t4;
        uint32_t arh[4], arl[4], aih[4], ail[4];
        arh[0]=*(const uint32_t*)(Arh+aoff);        arh[1]=*(const uint32_t*)(Arh+aoff+8*72);
        arh[2]=*(const uint32_t*)(Arh+aoff+8);      arh[3]=*(const uint32_t*)(Arh+aoff+8*72+8);
        arl[0]=*(const uint32_t*)(Arl+aoff);        arl[1]=*(const uint32_t*)(Arl+aoff+8*72);
        arl[2]=*(const uint32_t*)(Arl+aoff+8);      arl[3]=*(const uint32_t*)(Arl+aoff+8*72+8);
        aih[0]=*(const uint32_t*)(Aih+aoff);        aih[1]=*(const uint32_t*)(Aih+aoff+8*72);
        aih[2]=*(const uint32_t*)(Aih+aoff+8);      aih[3]=*(const uint32_t*)(Aih+aoff+8*72+8);
        ail[0]=*(const uint32_t*)(Ail+aoff);        ail[1]=*(const uint32_t*)(Ail+aoff+8*72);
        ail[2]=*(const uint32_t*)(Ail+aoff+8);      ail[3]=*(const uint32_t*)(Ail+aoff+8*72+8);
        #pragma unroll
        for (int nt = 0; nt < 4; nt++) {
            int boff = (n0 + nt * 8 + g) * 72 + ks * 16 + 2 * t4;
            uint32_t bh[2], bl[2];
            bh[0] = *(const uint32_t*)(Bh + boff);
            bh[1] = *(const uint32_t*)(Bh + boff + 8);
            bl[0] = *(const uint32_t*)(Bl + boff);
            bl[1] = *(const uint32_t*)(Bl + boff + 8);
            mma16816(accP[nt], arh, bh);
            mma16816(accP[nt], arh, bl);
            mma16816(accP[nt], arl, bh);
            mma16816(accQ[nt], aih, bh);
            mma16816(accQ[nt], aih, bl);
            mma16816(accQ[nt], ail, bh);
        }
    }
    float2* gt = g_Tmp + (size_t)bco * 256 * 32 + (size_t)hq * 64 * 32;
    #pragma unroll
    for (int nt = 0; nt < 4; nt++) {
        int col2 = (n0 >> 1) + nt * 4 + t4;
        gt[(m0 + g) * 32 + col2] = make_float2(accP[nt][0] - accQ[nt][1],
                                               accP[nt][1] + accQ[nt][0]);
        gt[(m0 + g + 8) * 32 + col2] = make_float2(accP[nt][2] - accQ[nt][3],
                                                   accP[nt][3] + accQ[nt][2]);
    }
}

// ============== K5: inverse real DFT along W via mma.sync ==============
#define IR_SMEM 73728
__global__ void __launch_bounds__(256) k_irfftW_m(float* __restrict__ out) {
    extern __shared__ unsigned char smem[];
    __nv_bfloat16* Ah = (__nv_bfloat16*)(smem);
    __nv_bfloat16* Al = (__nv_bfloat16*)(smem + 18432);
    __nv_bfloat16* Bh = (__nv_bfloat16*)(smem + 36864);
    __nv_bfloat16* Bl = (__nv_bfloat16*)(smem + 55296);
    int tid = threadIdx.x, lane = tid & 31, wid = tid >> 5;
    int g = lane >> 2, t4 = lane & 3;
    int rg = blockIdx.x >> 1, nh = blockIdx.x & 1;
    size_t rowBase = (size_t)rg * 128;

    const float4* ag = (const float4*)g_Tmp;
    #pragma unroll
    for (int i = 0; i < 8; i++) {
        int idx = tid + 256 * i;
        int r = idx >> 4, c4 = idx & 15;
        float4 v = ag[(rowBase + r) * 16 + c4];
        __nv_bfloat16 h0, h1, h2, h3, l0, l1, l2, l3;
        split_bf(v.x, h0, l0); split_bf(v.y, h1, l1);
        split_bf(v.z, h2, l2); split_bf(v.w, h3, l3);
        *(uint2*)(Ah + r * 72 + c4 * 4) = make_uint2(pack_bf(h0, h1), pack_bf(h2, h3));
        *(uint2*)(Al + r * 72 + c4 * 4) = make_uint2(pack_bf(l0, l1), pack_bf(l2, l3));
    }
    {
        const uint4* sh = ((const uint4*)g_BIh) + nh * 1152;
        const uint4* sl = ((const uint4*)g_BIl) + nh * 1152;
        uint4* dh = (uint4*)Bh; uint4* dl = (uint4*)Bl;
        for (int i = tid; i < 1152; i += 256) { dh[i] = sh[i]; dl[i] = sl[i]; }
    }
    __syncthreads();

    int m0 = (wid >> 1) * 32;
    int n0 = (wid & 1) * 64;
    float acc[2][8][4];
    #pragma unroll
    for (int mt = 0; mt < 2; mt++)
        #pragma unroll
        for (int nt = 0; nt < 8; nt++)
            #pragma unroll
            for (int i = 0; i < 4; i++) acc[mt][nt][i] = 0.f;

    #pragma unroll
    for (int ks = 0; ks < 4; ks++) {
        uint32_t ah[2][4], al[2][4];
        #pragma unroll
        for (int mt = 0; mt < 2; mt++) {
            int aoff = (m0 + mt * 16 + g) * 72 + ks * 16 + 2 * t4;
            ah[mt][0] = *(const uint32_t*)(Ah + aoff);
            ah[mt][1] = *(const uint32_t*)(Ah + aoff + 8 * 72);
            ah[mt][2] = *(const uint32_t*)(Ah + aoff + 8);
            ah[mt][3] = *(const uint32_t*)(Ah + aoff + 8 * 72 + 8);
            al[mt][0] = *(const uint32_t*)(Al + aoff);
            al[mt][1] = *(const uint32_t*)(Al + aoff + 8 * 72);
            al[mt][2] = *(const uint32_t*)(Al + aoff + 8);
            al[mt][3] = *(const uint32_t*)(Al + aoff + 8 * 72 + 8);
        }
        #pragma unroll
        for (int nt = 0; nt < 8; nt++) {
            int boff = (n0 + nt * 8 + g) * 72 + ks * 16 + 2 * t4;
            uint32_t bh[2], bl[2];
            bh[0] = *(const uint32_t*)(Bh + boff);
            bh[1] = *(const uint32_t*)(Bh + boff + 8);
            bl[0] = *(const uint32_t*)(Bl + boff);
            bl[1] = *(const uint32_t*)(Bl + boff + 8);
            #pragma unroll
            for (int mt = 0; mt < 2; mt++) {
                mma16816(acc[mt][nt], ah[mt], bh);
                mma16816(acc[mt][nt], ah[mt], bl);
                mma16816(acc[mt][nt], al[mt], bh);
            }
        }
    }
    #pragma unroll
    for (int mt = 0; mt < 2; mt++) {
        size_t r0 = rowBase + m0 + mt * 16 + g;
        #pragma unroll
        for (int nt = 0; nt < 8; nt++) {
            int col = nh * 128 + n0 + nt * 8 + 2 * t4;
            *(float2*)(out + r0 * 256 + col)       = make_float2(acc[mt][nt][0], acc[mt][nt][1]);
            *(float2*)(out + (r0 + 8) * 256 + col) = make_float2(acc[mt][nt][2], acc[mt][nt][3]);
        }
    }
}

extern "C" void kernel_launch(void* const* d_in, const int* in_sizes, int n_in,
                              void* d_out, int out_size) {
    const float* x   = (const float*)d_in[0];
    const float* fs  = (const float*)d_in[1];
    const float* w0  = (const float*)d_in[2];
    const float* w1  = (const float*)d_in[3];
    const float* we0 = (const float*)d_in[4];
    const float* we1 = (const float*)d_in[5];
    float* out = (float*)d_out;

    cudaFuncSetAttribute(k_fwdW_m,   cudaFuncAttributeMaxDynamicSharedMemorySize, FW_SMEM);
    cudaFuncSetAttribute(k_fwdH_m,   cudaFuncAttributeMaxDynamicSharedMemorySize, FH_SMEM);
    cudaFuncSetAttribute(k_invH_m,   cudaFuncAttributeMaxDynamicSharedMemorySize, IH_SMEM);
    cudaFuncSetAttribute(k_irfftW_m, cudaFuncAttributeMaxDynamicSharedMemorySize, IR_SMEM);

    k_init<<<288, 256>>>();
    k_wtrans<<<4096, 256>>>(w0, w1, we0, we1);
    k_fwdW_m<<<RTOT / 128, 256, FW_SMEM>>>(x);        // 1024 CTAs
    k_fwdH_m<<<Bsz * CIn * 2, 256, FH_SMEM>>>();      // 1024 CTAs
    k_mix<<<2 * 1024, 256>>>(fs);
    k_invH_m<<<Bsz * COn * 4, 256, IH_SMEM>>>();      // 2048 CTAs
    k_irfftW_m<<<RTOT / 64, 256, IR_SMEM>>>(out);     // 2048 CTAs
}